// round 14
// baseline (speedup 1.0000x reference)
#include <cuda_runtime.h>
#include <cuda_fp16.h>
#include <cstdint>

// Problem constants
static constexpr int N_CELL  = 50000;
static constexpr int N_NET   = 10000;
static constexpr int N_GCELL = 20000;
static constexpr int E       = 100000;
static constexpr int D       = 32;
static constexpr int N_PTOT  = N_NET + N_GCELL;                    // 30000 P rows
static constexpr int OUT_TOTAL = (N_CELL + N_NET + N_GCELL) * D;   // 2.56M

// Degree-counter layout
static constexpr int OFF_PINS_S   = 0;
static constexpr int OFF_PINS_D   = OFF_PINS_S + N_CELL;
static constexpr int OFF_CON_S    = OFF_PINS_D + N_NET;
static constexpr int OFF_CON_D    = OFF_CON_S + N_GCELL;
static constexpr int OFF_PT_S     = OFF_CON_D + N_GCELL;
static constexpr int OFF_PT_D     = OFF_PT_S + N_CELL;
static constexpr int OFF_PINNED_D = OFF_PT_D + N_GCELL;
static constexpr int OFF_PF_D     = OFF_PINNED_D + N_CELL;
static constexpr int DEG_TOTAL    = OFF_PF_D + N_CELL;             // 270000

// Scratch
__device__ int    g_deg[DEG_TOTAL];
__device__ float  g_feat_pins[N_CELL * D];
__device__ float  g_feat_pt[N_CELL * D];
__device__ float  g_feat_connect[N_GCELL * D];
__device__ __align__(16) __half g_P[(size_t)N_PTOT * 544];   // fp16 NNConv factor

// ---------------------------------------------------------------------------
// f32x2 packed-FMA helpers (Blackwell FFMA2)
typedef unsigned long long ull;
__device__ __forceinline__ ull f2pack(float lo, float hi) {
    ull r; asm("mov.b64 %0, {%1,%2};" : "=l"(r) : "f"(lo), "f"(hi)); return r;
}
__device__ __forceinline__ void f2unpack(ull v, float& lo, float& hi) {
    asm("mov.b64 {%0,%1}, %2;" : "=f"(lo), "=f"(hi) : "l"(v));
}
__device__ __forceinline__ ull ffma2(ull a, ull b, ull c) {
    ull d; asm("fma.rn.f32x2 %0, %1, %2, %3;" : "=l"(d) : "l"(a), "l"(b), "l"(c)); return d;
}

__device__ __forceinline__ void red_add_v4(float* addr, float x, float y, float z, float w) {
    asm volatile("red.global.add.v4.f32 [%0], {%1,%2,%3,%4};"
                 :: "l"(addr), "f"(x), "f"(y), "f"(z), "f"(w) : "memory");
}

// 8 halves (16B) -> 4 packed f32x2
struct F8 { ull v[4]; };
__device__ __forceinline__ F8 ldh8(const __half* p) {
    uint4 u = __ldg(reinterpret_cast<const uint4*>(p));
    unsigned uu[4] = {u.x, u.y, u.z, u.w};
    F8 r;
#pragma unroll
    for (int i = 0; i < 4; i++) {
        __half2 h = *reinterpret_cast<__half2*>(&uu[i]);
        float2 f = __half22float2(h);
        r.v[i] = f2pack(f.x, f.y);
    }
    return r;
}

__device__ __forceinline__ unsigned h2u(float lo, float hi) {
    __half2 h = __floats2half2_rn(lo, hi);
    return *reinterpret_cast<unsigned*>(&h);
}

// ---------------------------------------------------------------------------
// K1: fused init, vectorized x4: zero degree counters + bias sums into out.
static constexpr int INIT_V4 = OUT_TOTAL / 4;            // 640000
static constexpr int DEG_V4  = DEG_TOTAL / 4;            // 67500 (exact)
__global__ void init_fused_kernel(float* __restrict__ out,
                                  const float* __restrict__ b_pinned,
                                  const float* __restrict__ b_pf,
                                  const float* __restrict__ b_pins,
                                  const float* __restrict__ b_net,
                                  const float* __restrict__ b_connect,
                                  const float* __restrict__ b_pt) {
    int idx = blockIdx.x * blockDim.x + threadIdx.x;
    if (idx < DEG_V4)
        *reinterpret_cast<int4*>(&g_deg[idx * 4]) = make_int4(0, 0, 0, 0);
    if (idx >= INIT_V4) return;
    int elem = idx * 4;
    int row = elem >> 5;
    int j = elem & 31;
    float4 v;
    if (row < N_CELL)
        v = make_float4(b_pinned[j]   + b_pf[j],   b_pinned[j+1] + b_pf[j+1],
                        b_pinned[j+2] + b_pf[j+2], b_pinned[j+3] + b_pf[j+3]);
    else if (row < N_CELL + N_NET)
        v = make_float4(b_pins[j]   + b_net[j],   b_pins[j+1] + b_net[j+1],
                        b_pins[j+2] + b_net[j+2], b_pins[j+3] + b_net[j+3]);
    else
        v = make_float4(b_connect[j]   + b_pt[j],   b_connect[j+1] + b_pt[j+1],
                        b_connect[j+2] + b_pt[j+2], b_connect[j+3] + b_pt[j+3]);
    *reinterpret_cast<float4*>(&out[elem]) = v;
}

// ---------------------------------------------------------------------------
// K2: degree counting (first DEG_B blocks) + P-GEMM v2 (rest).
static constexpr int DEG_B     = (E + 255) / 256;        // 391
static constexpr int PG_TILES  = (N_PTOT + 63) / 64;     // 469
static constexpr int PG_BLOCKS = PG_TILES * 2;           // 938
static constexpr int K2_BLOCKS = DEG_B + PG_BLOCKS;      // 1329

__global__ __launch_bounds__(256, 2) void degree_pgemm_kernel(
        const float* __restrict__ net_feat,
        const float* __restrict__ hanna_feat,
        const float* __restrict__ W_topo,
        const int* __restrict__ pins_src, const int* __restrict__ pins_dst,
        const int* __restrict__ connect_src, const int* __restrict__ connect_dst,
        const int* __restrict__ pt_src, const int* __restrict__ pt_dst,
        const int* __restrict__ pinned_dst, const int* __restrict__ pf_dst) {
    __shared__ ull Asm[32 * 64];     // [k][row], (a,a) duplicated — 16 KB
    __shared__ ull Wsm[32 * 128];    // [k][colpair] — 32 KB

    int bid = blockIdx.x;
    int tid = threadIdx.x;

    // ---- degree blocks ----
    if (bid < DEG_B) {
        int e = bid * 256 + tid;
        if (e >= E) return;
        atomicAdd(&g_deg[OFF_PINS_S   + pins_src[e]], 1);
        atomicAdd(&g_deg[OFF_PINS_D   + pins_dst[e]], 1);
        atomicAdd(&g_deg[OFF_CON_S    + connect_src[e]], 1);
        atomicAdd(&g_deg[OFF_CON_D    + connect_dst[e]], 1);
        atomicAdd(&g_deg[OFF_PT_S     + pt_src[e]], 1);
        atomicAdd(&g_deg[OFF_PT_D     + pt_dst[e]], 1);
        atomicAdd(&g_deg[OFF_PINNED_D + pinned_dst[e]], 1);
        atomicAdd(&g_deg[OFF_PF_D     + pf_dst[e]], 1);
        return;
    }
    bid -= DEG_B;

    // ---- pgemm v2 body ----
    int tile    = bid >> 1;
    int colbase = (bid & 1) * 256;
    int n0      = tile * 64;

    for (int g = tid; g < 512; g += 256) {
        int row = g >> 3, seg = g & 7;
        int node = n0 + row;
        float4 x = make_float4(0.f, 0.f, 0.f, 0.f);
        if (node < N_PTOT) {
            const float* src = (node < N_NET) ? &net_feat[node * 32 + seg * 4]
                                              : &hanna_feat[(node - N_NET) * 32 + seg * 4];
            x = *reinterpret_cast<const float4*>(src);
        }
        Asm[(seg * 4 + 0) * 64 + row] = f2pack(x.x, x.x);
        Asm[(seg * 4 + 1) * 64 + row] = f2pack(x.y, x.y);
        Asm[(seg * 4 + 2) * 64 + row] = f2pack(x.z, x.z);
        Asm[(seg * 4 + 3) * 64 + row] = f2pack(x.w, x.w);
    }

    for (int g = tid; g < 2048; g += 256) {
        int k = g >> 6, p0 = (g & 63) * 2;
        int c0 = colbase + p0 * 2;
        int slot = c0 >> 5, j = c0 & 31;
        float4 w = *reinterpret_cast<const float4*>(&W_topo[slot * 1024 + k * 32 + j]);
        Wsm[k * 128 + p0]     = f2pack(w.x, w.y);
        Wsm[k * 128 + p0 + 1] = f2pack(w.z, w.w);
    }
    __syncthreads();

    int w  = tid >> 5;
    int wr = w >> 2, wc = w & 3;
    int lane = tid & 31;
    int ty = lane >> 3, tx = lane & 7;
    int rbase = wr * 32 + ty * 8;
    int pb    = wc * 32 + tx * 4;

    ull acc[8][4];
#pragma unroll
    for (int r = 0; r < 8; r++)
#pragma unroll
        for (int c = 0; c < 4; c++) acc[r][c] = 0ull;

#pragma unroll 4
    for (int k = 0; k < 32; k++) {
        const ulonglong2* Ap = reinterpret_cast<const ulonglong2*>(&Asm[k * 64 + rbase]);
        const ulonglong2* Wp = reinterpret_cast<const ulonglong2*>(&Wsm[k * 128 + pb]);
        ulonglong2 a01 = Ap[0], a23 = Ap[1], a45 = Ap[2], a67 = Ap[3];
        ulonglong2 w01 = Wp[0], w23 = Wp[1];
        ull a[8] = {a01.x, a01.y, a23.x, a23.y, a45.x, a45.y, a67.x, a67.y};
        ull wv[4] = {w01.x, w01.y, w23.x, w23.y};
#pragma unroll
        for (int r = 0; r < 8; r++)
#pragma unroll
            for (int c = 0; c < 4; c++)
                acc[r][c] = ffma2(a[r], wv[c], acc[r][c]);
    }

    int colg = colbase + wc * 64 + tx * 8;
#pragma unroll
    for (int r = 0; r < 8; r++) {
        int node = n0 + rbase + r;
        if (node >= N_PTOT) break;
        float l0, h0, l1, h1, l2, h2, l3, h3;
        f2unpack(acc[r][0], l0, h0);
        f2unpack(acc[r][1], l1, h1);
        f2unpack(acc[r][2], l2, h2);
        f2unpack(acc[r][3], l3, h3);
        uint4 o = make_uint4(h2u(l0, h0), h2u(l1, h1), h2u(l2, h2), h2u(l3, h3));
        *reinterpret_cast<uint4*>(&g_P[(size_t)node * 544 + colg]) = o;
    }
}

// ---------------------------------------------------------------------------
// K3: remaining dense jobs v3: 128-row x 64-col tiles, 4x8 thread tiles.
static constexpr int ND_DUAL = (N_CELL + 127) / 128;   // 391
static constexpr int ND_B    = (N_NET + 127) / 128;    // 79
static constexpr int ND_C    = (N_GCELL + 127) / 128;  // 157
static constexpr int NB_REST = ND_DUAL + ND_B + ND_C;  // 627

__global__ __launch_bounds__(256, 3) void dense_rest_kernel(
        const float* __restrict__ node_feat,
        const float* __restrict__ net_feat,
        const float* __restrict__ hanna_feat,
        const float* __restrict__ b_topo,
        const float* __restrict__ W_pins, const float* __restrict__ W_pt,
        const float* __restrict__ W_connect, const float* __restrict__ W_net,
        float* __restrict__ out_net) {
    __shared__ ull Am[32 * 130];     // [k][row] (a,a) dup, stride 130 — 33.3 KB
    __shared__ ull Wm[32 * 32];      // [k][pair] — 8.2 KB

    int bid = blockIdx.x;
    int tid = threadIdx.x;

    int jobtype, tile;
    if (bid < ND_DUAL)            { jobtype = 0; tile = bid; }
    else if (bid < ND_DUAL + ND_B){ jobtype = 1; tile = bid - ND_DUAL; }
    else                          { jobtype = 2; tile = bid - ND_DUAL - ND_B; }

    int n0 = tile * 128;
    int nrows = (jobtype == 0) ? N_CELL : (jobtype == 1) ? N_NET : N_GCELL;
    const float* X  = (jobtype == 0) ? node_feat : (jobtype == 1) ? net_feat : hanna_feat;
    const float* W1 = (jobtype == 0) ? W_pins : b_topo;
    const float* W2 = (jobtype == 0) ? W_pt : (jobtype == 1) ? W_net : W_connect;

    for (int g = tid; g < 1024; g += 256) {
        int row = g >> 3, seg = g & 7;
        int node = n0 + row;
        float4 x = make_float4(0.f, 0.f, 0.f, 0.f);
        if (node < nrows)
            x = *reinterpret_cast<const float4*>(&X[node * 32 + seg * 4]);
        Am[(seg * 4 + 0) * 130 + row] = f2pack(x.x, x.x);
        Am[(seg * 4 + 1) * 130 + row] = f2pack(x.y, x.y);
        Am[(seg * 4 + 2) * 130 + row] = f2pack(x.z, x.z);
        Am[(seg * 4 + 3) * 130 + row] = f2pack(x.w, x.w);
    }

    for (int g = tid; g < 512; g += 256) {
        int k = g >> 4, ph = g & 15;
        const float* src = (ph < 8) ? &W1[k * 32 + ph * 4] : &W2[k * 32 + (ph - 8) * 4];
        float4 wv = *reinterpret_cast<const float4*>(src);
        Wm[k * 32 + ph * 2]     = f2pack(wv.x, wv.y);
        Wm[k * 32 + ph * 2 + 1] = f2pack(wv.z, wv.w);
    }
    __syncthreads();

    int rg = tid >> 3, pg = tid & 7;
    int rbase = rg * 4, pb = pg * 4;

    ull acc[4][4];
#pragma unroll
    for (int r = 0; r < 4; r++)
#pragma unroll
        for (int c = 0; c < 4; c++) acc[r][c] = 0ull;

#pragma unroll 2
    for (int k = 0; k < 32; k++) {
        const ulonglong2* Ap = reinterpret_cast<const ulonglong2*>(&Am[k * 130 + rbase]);
        const ulonglong2* Wp = reinterpret_cast<const ulonglong2*>(&Wm[k * 32 + pb]);
        ulonglong2 a01 = Ap[0], a23 = Ap[1];
        ulonglong2 w01 = Wp[0], w23 = Wp[1];
        ull a[4]  = {a01.x, a01.y, a23.x, a23.y};
        ull wv[4] = {w01.x, w01.y, w23.x, w23.y};
#pragma unroll
        for (int r = 0; r < 4; r++)
#pragma unroll
            for (int c = 0; c < 4; c++)
                acc[r][c] = ffma2(a[r], wv[c], acc[r][c]);
    }

    bool first = (pg < 4);
    int c0 = (first ? pg : pg - 4) * 8;
#pragma unroll
    for (int r = 0; r < 4; r++) {
        int node = n0 + rbase + r;
        if (node >= nrows) break;
        float v0, v1, v2, v3, v4, v5, v6, v7;
        f2unpack(acc[r][0], v0, v1);
        f2unpack(acc[r][1], v2, v3);
        f2unpack(acc[r][2], v4, v5);
        f2unpack(acc[r][3], v6, v7);

        if (jobtype == 0) {
            float s; float* dst;
            if (first) { s = rsqrtf((float)max(g_deg[OFF_PINS_S + node], 1)); dst = &g_feat_pins[node * 32 + c0]; }
            else       { s = rsqrtf((float)max(g_deg[OFF_PT_S   + node], 1)); dst = &g_feat_pt[node * 32 + c0]; }
            *reinterpret_cast<float4*>(dst)     = make_float4(v0 * s, v1 * s, v2 * s, v3 * s);
            *reinterpret_cast<float4*>(dst + 4) = make_float4(v4 * s, v5 * s, v6 * s, v7 * s);
        } else if (first) {
            int prow = (jobtype == 1) ? node : node + N_NET;
            uint4 o = make_uint4(h2u(v0, v1), h2u(v2, v3), h2u(v4, v5), h2u(v6, v7));
            *reinterpret_cast<uint4*>(&g_P[(size_t)prow * 544 + 512 + c0]) = o;
        } else if (jobtype == 1) {
            float4* o = reinterpret_cast<float4*>(&out_net[node * 32 + c0]);
            float4 a0 = o[0], a1 = o[1];
            o[0] = make_float4(a0.x + v0, a0.y + v1, a0.z + v2, a0.w + v3);
            o[1] = make_float4(a1.x + v4, a1.y + v5, a1.z + v6, a1.w + v7);
        } else {
            float s = rsqrtf((float)max(g_deg[OFF_CON_S + node], 1));
            float* dst = &g_feat_connect[node * 32 + c0];
            *reinterpret_cast<float4*>(dst)     = make_float4(v0 * s, v1 * s, v2 * s, v3 * s);
            *reinterpret_cast<float4*>(dst + 4) = make_float4(v4 * s, v5 * s, v6 * s, v7 * s);
        }
    }
}

// ---------------------------------------------------------------------------
// K4: all 5 edge relations, 4 edges/warp (8 lanes/edge).
// R3 sequential-relation structure; NNConv P gathers upgraded to LDG.128 with
// even/odd-k lane split (lanes q<4: even k + bias; q>=4: odd k; 8 cols each).
__global__ __launch_bounds__(256) void edge_kernel(
        const int* __restrict__ pins_src, const int* __restrict__ pins_dst,
        const int* __restrict__ con_src,  const int* __restrict__ con_dst,
        const int* __restrict__ pt_src,   const int* __restrict__ pt_dst,
        const int* __restrict__ pinned_src, const int* __restrict__ pinned_dst,
        const int* __restrict__ pf_src,   const int* __restrict__ pf_dst,
        const float* __restrict__ pin_feat, const float* __restrict__ edge_feat,
        float* __restrict__ out_cell, float* __restrict__ out_net, float* __restrict__ out_gcell) {
    int t = blockIdx.x * blockDim.x + threadIdx.x;
    int lane = t & 31;
    int e = ((t >> 5) << 2) + (lane >> 3);     // 4 edges per warp
    if (e >= E) return;
    int q = lane & 7;
    int baseLane = lane & 24;

    // --- GraphConv scatters (sequential, as in proven R3 form) ---
    {
        int s = pins_src[e], d = pins_dst[e];
        float4 v = *reinterpret_cast<const float4*>(&g_feat_pins[s * 32 + q * 4]);
        float sc = rsqrtf((float)max(g_deg[OFF_PINS_D + d], 1));
        red_add_v4(out_net + d * 32 + q * 4, v.x * sc, v.y * sc, v.z * sc, v.w * sc);
    }
    {
        int s = con_src[e], d = con_dst[e];
        float4 v = *reinterpret_cast<const float4*>(&g_feat_connect[s * 32 + q * 4]);
        float sc = rsqrtf((float)max(g_deg[OFF_CON_D + d], 1));
        red_add_v4(out_gcell + d * 32 + q * 4, v.x * sc, v.y * sc, v.z * sc, v.w * sc);
    }
    {
        int s = pt_src[e], d = pt_dst[e];
        float4 v = *reinterpret_cast<const float4*>(&g_feat_pt[s * 32 + q * 4]);
        float sc = rsqrtf((float)max(g_deg[OFF_PT_D + d], 1));
        red_add_v4(out_gcell + d * 32 + q * 4, v.x * sc, v.y * sc, v.z * sc, v.w * sc);
    }

    // --- NNConv edges: even/odd-k lane split, 16B P loads ---
    {
        int g = q >> 2;          // 0: even k (+bias), 1: odd k
        int c4 = q & 3;          // 8-col chunk
        int sA = pinned_src[e], dA = pinned_dst[e];
        int sB = pf_src[e] + N_NET, dB = pf_dst[e];
        float evA0 = pin_feat[e * 16 + q],  evA1 = pin_feat[e * 16 + 8 + q];
        float evB0 = edge_feat[e * 16 + q], evB1 = edge_feat[e * 16 + 8 + q];

        const __half* PA = g_P + (size_t)sA * 544;
        const __half* PB = g_P + (size_t)sB * 544;

        F8 accA, accB;
        if (g == 0) { accA = ldh8(PA + 512 + c4 * 8); accB = ldh8(PB + 512 + c4 * 8); }
        else {
#pragma unroll
            for (int i = 0; i < 4; i++) { accA.v[i] = 0ull; accB.v[i] = 0ull; }
        }

#pragma unroll
        for (int kk = 0; kk < 8; kk++) {
            int k = kk * 2 + g;
            float cA = __shfl_sync(0xffffffffu, (kk < 4) ? evA0 : evA1, baseLane + (k & 7));
            float cB = __shfl_sync(0xffffffffu, (kk < 4) ? evB0 : evB1, baseLane + (k & 7));
            ull ccA = f2pack(cA, cA);
            ull ccB = f2pack(cB, cB);
            F8 pa = ldh8(PA + k * 32 + c4 * 8);
            F8 pb = ldh8(PB + k * 32 + c4 * 8);
#pragma unroll
            for (int i = 0; i < 4; i++) {
                accA.v[i] = ffma2(pa.v[i], ccA, accA.v[i]);
                accB.v[i] = ffma2(pb.v[i], ccB, accB.v[i]);
            }
        }

        float invA = 1.0f / (float)max(g_deg[OFF_PINNED_D + dA], 1);
        float invB = 1.0f / (float)max(g_deg[OFF_PF_D + dB], 1);

        float a0, a1, a2, a3, a4, a5, a6, a7;
        f2unpack(accA.v[0], a0, a1); f2unpack(accA.v[1], a2, a3);
        f2unpack(accA.v[2], a4, a5); f2unpack(accA.v[3], a6, a7);
        red_add_v4(out_cell + dA * 32 + c4 * 8,     a0 * invA, a1 * invA, a2 * invA, a3 * invA);
        red_add_v4(out_cell + dA * 32 + c4 * 8 + 4, a4 * invA, a5 * invA, a6 * invA, a7 * invA);

        f2unpack(accB.v[0], a0, a1); f2unpack(accB.v[1], a2, a3);
        f2unpack(accB.v[2], a4, a5); f2unpack(accB.v[3], a6, a7);
        red_add_v4(out_cell + dB * 32 + c4 * 8,     a0 * invB, a1 * invB, a2 * invB, a3 * invB);
        red_add_v4(out_cell + dB * 32 + c4 * 8 + 4, a4 * invB, a5 * invB, a6 * invB, a7 * invB);
    }
}

// ---------------------------------------------------------------------------
extern "C" void kernel_launch(void* const* d_in, const int* in_sizes, int n_in,
                              void* d_out, int out_size) {
    const float* node_feat   = (const float*)d_in[0];
    const float* net_feat    = (const float*)d_in[1];
    const float* pin_feat    = (const float*)d_in[2];
    const float* hanna_feat  = (const float*)d_in[3];
    const float* edge_feat   = (const float*)d_in[4];
    const int*   pins_src    = (const int*)d_in[5];
    const int*   pins_dst    = (const int*)d_in[6];
    const int*   pinned_src  = (const int*)d_in[7];
    const int*   pinned_dst  = (const int*)d_in[8];
    const int*   connect_src = (const int*)d_in[9];
    const int*   connect_dst = (const int*)d_in[10];
    const int*   pt_src      = (const int*)d_in[11];
    const int*   pt_dst      = (const int*)d_in[12];
    const int*   pf_src      = (const int*)d_in[13];
    const int*   pf_dst      = (const int*)d_in[14];
    const float* W_net       = (const float*)d_in[15];
    const float* b_net       = (const float*)d_in[16];
    const float* W_topo      = (const float*)d_in[17];
    const float* b_topo      = (const float*)d_in[18];
    const float* W_pins      = (const float*)d_in[19];
    const float* b_pins      = (const float*)d_in[20];
    const float* W_connect   = (const float*)d_in[21];
    const float* b_connect   = (const float*)d_in[22];
    const float* W_pt        = (const float*)d_in[23];
    const float* b_pt        = (const float*)d_in[24];
    const float* b_pinned    = (const float*)d_in[25];
    const float* b_pf        = (const float*)d_in[26];

    float* out       = (float*)d_out;
    float* out_net   = out + (size_t)N_CELL * D;
    float* out_gcell = out + (size_t)(N_CELL + N_NET) * D;

    // K1: fused init (zero degrees + bias-sum output init), vectorized
    init_fused_kernel<<<(INIT_V4 + 255) / 256, 256>>>(out, b_pinned, b_pf, b_pins, b_net,
                                                      b_connect, b_pt);

    // K2: degree counting overlapped with P-GEMM (independent work, one launch)
    degree_pgemm_kernel<<<K2_BLOCKS, 256>>>(net_feat, hanna_feat, W_topo,
                                            pins_src, pins_dst, connect_src, connect_dst,
                                            pt_src, pt_dst, pinned_dst, pf_dst);

    // K3: remaining dense jobs (v3 tiles — measured best)
    dense_rest_kernel<<<NB_REST, 256>>>(node_feat, net_feat, hanna_feat,
                                        b_topo, W_pins, W_pt, W_connect, W_net, out_net);

    // K4: all 5 edge relations (R3 structure + 16B NNConv loads)
    const int EGRID = (E / 4 * 32 + 255) / 256;   // 3125 blocks
    edge_kernel<<<EGRID, 256>>>(pins_src, pins_dst, connect_src, connect_dst,
                                pt_src, pt_dst, pinned_src, pinned_dst, pf_src, pf_dst,
                                pin_feat, edge_feat, out, out_net, out_gcell);
}

// round 15
// speedup vs baseline: 1.1298x; 1.1298x over previous
#include <cuda_runtime.h>
#include <cuda_fp16.h>
#include <cstdint>

// Problem constants
static constexpr int N_CELL  = 50000;
static constexpr int N_NET   = 10000;
static constexpr int N_GCELL = 20000;
static constexpr int E       = 100000;
static constexpr int D       = 32;
static constexpr int N_PTOT  = N_NET + N_GCELL;                    // 30000 P rows
static constexpr int OUT_TOTAL = (N_CELL + N_NET + N_GCELL) * D;   // 2.56M

// Degree-counter layout
static constexpr int OFF_PINS_S   = 0;
static constexpr int OFF_PINS_D   = OFF_PINS_S + N_CELL;
static constexpr int OFF_CON_S    = OFF_PINS_D + N_NET;
static constexpr int OFF_CON_D    = OFF_CON_S + N_GCELL;
static constexpr int OFF_PT_S     = OFF_CON_D + N_GCELL;
static constexpr int OFF_PT_D     = OFF_PT_S + N_CELL;
static constexpr int OFF_PINNED_D = OFF_PT_D + N_GCELL;
static constexpr int OFF_PF_D     = OFF_PINNED_D + N_CELL;
static constexpr int DEG_TOTAL    = OFF_PF_D + N_CELL;             // 270000

// Scratch — GraphConv feats now fp16 (halves edge-gather wavefronts/bytes)
__device__ int    g_deg[DEG_TOTAL];
__device__ __align__(16) __half g_feat_pins[N_CELL * D];
__device__ __align__(16) __half g_feat_pt[N_CELL * D];
__device__ __align__(16) __half g_feat_connect[N_GCELL * D];
__device__ __align__(16) __half g_P[(size_t)N_PTOT * 544];   // fp16 NNConv factor

// ---------------------------------------------------------------------------
// f32x2 packed-FMA helpers (Blackwell FFMA2)
typedef unsigned long long ull;
__device__ __forceinline__ ull f2pack(float lo, float hi) {
    ull r; asm("mov.b64 %0, {%1,%2};" : "=l"(r) : "f"(lo), "f"(hi)); return r;
}
__device__ __forceinline__ void f2unpack(ull v, float& lo, float& hi) {
    asm("mov.b64 {%0,%1}, %2;" : "=f"(lo), "=f"(hi) : "l"(v));
}
__device__ __forceinline__ ull ffma2(ull a, ull b, ull c) {
    ull d; asm("fma.rn.f32x2 %0, %1, %2, %3;" : "=l"(d) : "l"(a), "l"(b), "l"(c)); return d;
}

__device__ __forceinline__ void red_add_v4(float* addr, float x, float y, float z, float w) {
    asm volatile("red.global.add.v4.f32 [%0], {%1,%2,%3,%4};"
                 :: "l"(addr), "f"(x), "f"(y), "f"(z), "f"(w) : "memory");
}

// 4 halves (8B) -> float4
__device__ __forceinline__ float4 ldh4(const __half* p) {
    uint2 u = __ldg(reinterpret_cast<const uint2*>(p));
    __half2 h0 = *reinterpret_cast<__half2*>(&u.x);
    __half2 h1 = *reinterpret_cast<__half2*>(&u.y);
    float2 f0 = __half22float2(h0);
    float2 f1 = __half22float2(h1);
    return make_float4(f0.x, f0.y, f1.x, f1.y);
}

__device__ __forceinline__ unsigned h2u(float lo, float hi) {
    __half2 h = __floats2half2_rn(lo, hi);
    return *reinterpret_cast<unsigned*>(&h);
}

// ---------------------------------------------------------------------------
// K1: fused init, vectorized x4: zero degree counters + bias sums into out.
static constexpr int INIT_V4 = OUT_TOTAL / 4;            // 640000
static constexpr int DEG_V4  = DEG_TOTAL / 4;            // 67500 (exact)
__global__ void init_fused_kernel(float* __restrict__ out,
                                  const float* __restrict__ b_pinned,
                                  const float* __restrict__ b_pf,
                                  const float* __restrict__ b_pins,
                                  const float* __restrict__ b_net,
                                  const float* __restrict__ b_connect,
                                  const float* __restrict__ b_pt) {
    int idx = blockIdx.x * blockDim.x + threadIdx.x;
    if (idx < DEG_V4)
        *reinterpret_cast<int4*>(&g_deg[idx * 4]) = make_int4(0, 0, 0, 0);
    if (idx >= INIT_V4) return;
    int elem = idx * 4;
    int row = elem >> 5;
    int j = elem & 31;
    float4 v;
    if (row < N_CELL)
        v = make_float4(b_pinned[j]   + b_pf[j],   b_pinned[j+1] + b_pf[j+1],
                        b_pinned[j+2] + b_pf[j+2], b_pinned[j+3] + b_pf[j+3]);
    else if (row < N_CELL + N_NET)
        v = make_float4(b_pins[j]   + b_net[j],   b_pins[j+1] + b_net[j+1],
                        b_pins[j+2] + b_net[j+2], b_pins[j+3] + b_net[j+3]);
    else
        v = make_float4(b_connect[j]   + b_pt[j],   b_connect[j+1] + b_pt[j+1],
                        b_connect[j+2] + b_pt[j+2], b_connect[j+3] + b_pt[j+3]);
    *reinterpret_cast<float4*>(&out[elem]) = v;
}

// ---------------------------------------------------------------------------
// K2: degree counting (first DEG_B blocks) + P-GEMM v2 (rest).
static constexpr int DEG_B     = (E + 255) / 256;        // 391
static constexpr int PG_TILES  = (N_PTOT + 63) / 64;     // 469
static constexpr int PG_BLOCKS = PG_TILES * 2;           // 938
static constexpr int K2_BLOCKS = DEG_B + PG_BLOCKS;      // 1329

__global__ __launch_bounds__(256, 2) void degree_pgemm_kernel(
        const float* __restrict__ net_feat,
        const float* __restrict__ hanna_feat,
        const float* __restrict__ W_topo,
        const int* __restrict__ pins_src, const int* __restrict__ pins_dst,
        const int* __restrict__ connect_src, const int* __restrict__ connect_dst,
        const int* __restrict__ pt_src, const int* __restrict__ pt_dst,
        const int* __restrict__ pinned_dst, const int* __restrict__ pf_dst) {
    __shared__ ull Asm[32 * 64];     // [k][row], (a,a) duplicated — 16 KB
    __shared__ ull Wsm[32 * 128];    // [k][colpair] — 32 KB

    int bid = blockIdx.x;
    int tid = threadIdx.x;

    // ---- degree blocks ----
    if (bid < DEG_B) {
        int e = bid * 256 + tid;
        if (e >= E) return;
        atomicAdd(&g_deg[OFF_PINS_S   + pins_src[e]], 1);
        atomicAdd(&g_deg[OFF_PINS_D   + pins_dst[e]], 1);
        atomicAdd(&g_deg[OFF_CON_S    + connect_src[e]], 1);
        atomicAdd(&g_deg[OFF_CON_D    + connect_dst[e]], 1);
        atomicAdd(&g_deg[OFF_PT_S     + pt_src[e]], 1);
        atomicAdd(&g_deg[OFF_PT_D     + pt_dst[e]], 1);
        atomicAdd(&g_deg[OFF_PINNED_D + pinned_dst[e]], 1);
        atomicAdd(&g_deg[OFF_PF_D     + pf_dst[e]], 1);
        return;
    }
    bid -= DEG_B;

    // ---- pgemm v2 body ----
    int tile    = bid >> 1;
    int colbase = (bid & 1) * 256;
    int n0      = tile * 64;

    for (int g = tid; g < 512; g += 256) {
        int row = g >> 3, seg = g & 7;
        int node = n0 + row;
        float4 x = make_float4(0.f, 0.f, 0.f, 0.f);
        if (node < N_PTOT) {
            const float* src = (node < N_NET) ? &net_feat[node * 32 + seg * 4]
                                              : &hanna_feat[(node - N_NET) * 32 + seg * 4];
            x = *reinterpret_cast<const float4*>(src);
        }
        Asm[(seg * 4 + 0) * 64 + row] = f2pack(x.x, x.x);
        Asm[(seg * 4 + 1) * 64 + row] = f2pack(x.y, x.y);
        Asm[(seg * 4 + 2) * 64 + row] = f2pack(x.z, x.z);
        Asm[(seg * 4 + 3) * 64 + row] = f2pack(x.w, x.w);
    }

    for (int g = tid; g < 2048; g += 256) {
        int k = g >> 6, p0 = (g & 63) * 2;
        int c0 = colbase + p0 * 2;
        int slot = c0 >> 5, j = c0 & 31;
        float4 w = *reinterpret_cast<const float4*>(&W_topo[slot * 1024 + k * 32 + j]);
        Wsm[k * 128 + p0]     = f2pack(w.x, w.y);
        Wsm[k * 128 + p0 + 1] = f2pack(w.z, w.w);
    }
    __syncthreads();

    int w  = tid >> 5;
    int wr = w >> 2, wc = w & 3;
    int lane = tid & 31;
    int ty = lane >> 3, tx = lane & 7;
    int rbase = wr * 32 + ty * 8;
    int pb    = wc * 32 + tx * 4;

    ull acc[8][4];
#pragma unroll
    for (int r = 0; r < 8; r++)
#pragma unroll
        for (int c = 0; c < 4; c++) acc[r][c] = 0ull;

#pragma unroll 4
    for (int k = 0; k < 32; k++) {
        const ulonglong2* Ap = reinterpret_cast<const ulonglong2*>(&Asm[k * 64 + rbase]);
        const ulonglong2* Wp = reinterpret_cast<const ulonglong2*>(&Wsm[k * 128 + pb]);
        ulonglong2 a01 = Ap[0], a23 = Ap[1], a45 = Ap[2], a67 = Ap[3];
        ulonglong2 w01 = Wp[0], w23 = Wp[1];
        ull a[8] = {a01.x, a01.y, a23.x, a23.y, a45.x, a45.y, a67.x, a67.y};
        ull wv[4] = {w01.x, w01.y, w23.x, w23.y};
#pragma unroll
        for (int r = 0; r < 8; r++)
#pragma unroll
            for (int c = 0; c < 4; c++)
                acc[r][c] = ffma2(a[r], wv[c], acc[r][c]);
    }

    int colg = colbase + wc * 64 + tx * 8;
#pragma unroll
    for (int r = 0; r < 8; r++) {
        int node = n0 + rbase + r;
        if (node >= N_PTOT) break;
        float l0, h0, l1, h1, l2, h2, l3, h3;
        f2unpack(acc[r][0], l0, h0);
        f2unpack(acc[r][1], l1, h1);
        f2unpack(acc[r][2], l2, h2);
        f2unpack(acc[r][3], l3, h3);
        uint4 o = make_uint4(h2u(l0, h0), h2u(l1, h1), h2u(l2, h2), h2u(l3, h3));
        *reinterpret_cast<uint4*>(&g_P[(size_t)node * 544 + colg]) = o;
    }
}

// ---------------------------------------------------------------------------
// K3: remaining dense jobs v3: 128-row x 64-col tiles, 4x8 thread tiles.
// GraphConv feat outputs now packed to fp16.
static constexpr int ND_DUAL = (N_CELL + 127) / 128;   // 391
static constexpr int ND_B    = (N_NET + 127) / 128;    // 79
static constexpr int ND_C    = (N_GCELL + 127) / 128;  // 157
static constexpr int NB_REST = ND_DUAL + ND_B + ND_C;  // 627

__global__ __launch_bounds__(256, 3) void dense_rest_kernel(
        const float* __restrict__ node_feat,
        const float* __restrict__ net_feat,
        const float* __restrict__ hanna_feat,
        const float* __restrict__ b_topo,
        const float* __restrict__ W_pins, const float* __restrict__ W_pt,
        const float* __restrict__ W_connect, const float* __restrict__ W_net,
        float* __restrict__ out_net) {
    __shared__ ull Am[32 * 130];     // [k][row] (a,a) dup, stride 130 — 33.3 KB
    __shared__ ull Wm[32 * 32];      // [k][pair] — 8.2 KB

    int bid = blockIdx.x;
    int tid = threadIdx.x;

    int jobtype, tile;
    if (bid < ND_DUAL)            { jobtype = 0; tile = bid; }
    else if (bid < ND_DUAL + ND_B){ jobtype = 1; tile = bid - ND_DUAL; }
    else                          { jobtype = 2; tile = bid - ND_DUAL - ND_B; }

    int n0 = tile * 128;
    int nrows = (jobtype == 0) ? N_CELL : (jobtype == 1) ? N_NET : N_GCELL;
    const float* X  = (jobtype == 0) ? node_feat : (jobtype == 1) ? net_feat : hanna_feat;
    const float* W1 = (jobtype == 0) ? W_pins : b_topo;
    const float* W2 = (jobtype == 0) ? W_pt : (jobtype == 1) ? W_net : W_connect;

    for (int g = tid; g < 1024; g += 256) {
        int row = g >> 3, seg = g & 7;
        int node = n0 + row;
        float4 x = make_float4(0.f, 0.f, 0.f, 0.f);
        if (node < nrows)
            x = *reinterpret_cast<const float4*>(&X[node * 32 + seg * 4]);
        Am[(seg * 4 + 0) * 130 + row] = f2pack(x.x, x.x);
        Am[(seg * 4 + 1) * 130 + row] = f2pack(x.y, x.y);
        Am[(seg * 4 + 2) * 130 + row] = f2pack(x.z, x.z);
        Am[(seg * 4 + 3) * 130 + row] = f2pack(x.w, x.w);
    }

    for (int g = tid; g < 512; g += 256) {
        int k = g >> 4, ph = g & 15;
        const float* src = (ph < 8) ? &W1[k * 32 + ph * 4] : &W2[k * 32 + (ph - 8) * 4];
        float4 wv = *reinterpret_cast<const float4*>(src);
        Wm[k * 32 + ph * 2]     = f2pack(wv.x, wv.y);
        Wm[k * 32 + ph * 2 + 1] = f2pack(wv.z, wv.w);
    }
    __syncthreads();

    int rg = tid >> 3, pg = tid & 7;
    int rbase = rg * 4, pb = pg * 4;

    ull acc[4][4];
#pragma unroll
    for (int r = 0; r < 4; r++)
#pragma unroll
        for (int c = 0; c < 4; c++) acc[r][c] = 0ull;

#pragma unroll 2
    for (int k = 0; k < 32; k++) {
        const ulonglong2* Ap = reinterpret_cast<const ulonglong2*>(&Am[k * 130 + rbase]);
        const ulonglong2* Wp = reinterpret_cast<const ulonglong2*>(&Wm[k * 32 + pb]);
        ulonglong2 a01 = Ap[0], a23 = Ap[1];
        ulonglong2 w01 = Wp[0], w23 = Wp[1];
        ull a[4]  = {a01.x, a01.y, a23.x, a23.y};
        ull wv[4] = {w01.x, w01.y, w23.x, w23.y};
#pragma unroll
        for (int r = 0; r < 4; r++)
#pragma unroll
            for (int c = 0; c < 4; c++)
                acc[r][c] = ffma2(a[r], wv[c], acc[r][c]);
    }

    bool first = (pg < 4);
    int c0 = (first ? pg : pg - 4) * 8;
#pragma unroll
    for (int r = 0; r < 4; r++) {
        int node = n0 + rbase + r;
        if (node >= nrows) break;
        float v0, v1, v2, v3, v4, v5, v6, v7;
        f2unpack(acc[r][0], v0, v1);
        f2unpack(acc[r][1], v2, v3);
        f2unpack(acc[r][2], v4, v5);
        f2unpack(acc[r][3], v6, v7);

        if (jobtype == 0) {
            float s; __half* dst;
            if (first) { s = rsqrtf((float)max(g_deg[OFF_PINS_S + node], 1)); dst = &g_feat_pins[node * 32 + c0]; }
            else       { s = rsqrtf((float)max(g_deg[OFF_PT_S   + node], 1)); dst = &g_feat_pt[node * 32 + c0]; }
            uint4 o = make_uint4(h2u(v0 * s, v1 * s), h2u(v2 * s, v3 * s),
                                 h2u(v4 * s, v5 * s), h2u(v6 * s, v7 * s));
            *reinterpret_cast<uint4*>(dst) = o;
        } else if (first) {
            int prow = (jobtype == 1) ? node : node + N_NET;
            uint4 o = make_uint4(h2u(v0, v1), h2u(v2, v3), h2u(v4, v5), h2u(v6, v7));
            *reinterpret_cast<uint4*>(&g_P[(size_t)prow * 544 + 512 + c0]) = o;
        } else if (jobtype == 1) {
            float4* o = reinterpret_cast<float4*>(&out_net[node * 32 + c0]);
            float4 a0 = o[0], a1 = o[1];
            o[0] = make_float4(a0.x + v0, a0.y + v1, a0.z + v2, a0.w + v3);
            o[1] = make_float4(a1.x + v4, a1.y + v5, a1.z + v6, a1.w + v7);
        } else {
            float s = rsqrtf((float)max(g_deg[OFF_CON_S + node], 1));
            __half* dst = &g_feat_connect[node * 32 + c0];
            uint4 o = make_uint4(h2u(v0 * s, v1 * s), h2u(v2 * s, v3 * s),
                                 h2u(v4 * s, v5 * s), h2u(v6 * s, v7 * s));
            *reinterpret_cast<uint4*>(dst) = o;
        }
    }
}

// ---------------------------------------------------------------------------
// K4: all 5 edge relations, 4 edges/warp (8 lanes/edge) — R3/R13 proven form,
// with fp16 GraphConv feat gathers (8B loads, half the wavefronts).
__global__ __launch_bounds__(256) void edge_kernel(
        const int* __restrict__ pins_src, const int* __restrict__ pins_dst,
        const int* __restrict__ con_src,  const int* __restrict__ con_dst,
        const int* __restrict__ pt_src,   const int* __restrict__ pt_dst,
        const int* __restrict__ pinned_src, const int* __restrict__ pinned_dst,
        const int* __restrict__ pf_src,   const int* __restrict__ pf_dst,
        const float* __restrict__ pin_feat, const float* __restrict__ edge_feat,
        float* __restrict__ out_cell, float* __restrict__ out_net, float* __restrict__ out_gcell) {
    int t = blockIdx.x * blockDim.x + threadIdx.x;
    int lane = t & 31;
    int e = ((t >> 5) << 2) + (lane >> 3);     // 4 edges per warp
    if (e >= E) return;
    int q = lane & 7;
    int baseLane = lane & 24;

    // --- GraphConv scatters: out[dst] += feat[src] * rsqrt(deg_dst) ---
    {
        int s = pins_src[e], d = pins_dst[e];
        float4 v = ldh4(&g_feat_pins[s * 32 + q * 4]);
        float sc = rsqrtf((float)max(g_deg[OFF_PINS_D + d], 1));
        red_add_v4(out_net + d * 32 + q * 4, v.x * sc, v.y * sc, v.z * sc, v.w * sc);
    }
    {
        int s = con_src[e], d = con_dst[e];
        float4 v = ldh4(&g_feat_connect[s * 32 + q * 4]);
        float sc = rsqrtf((float)max(g_deg[OFF_CON_D + d], 1));
        red_add_v4(out_gcell + d * 32 + q * 4, v.x * sc, v.y * sc, v.z * sc, v.w * sc);
    }
    {
        int s = pt_src[e], d = pt_dst[e];
        float4 v = ldh4(&g_feat_pt[s * 32 + q * 4]);
        float sc = rsqrtf((float)max(g_deg[OFF_PT_D + d], 1));
        red_add_v4(out_gcell + d * 32 + q * 4, v.x * sc, v.y * sc, v.z * sc, v.w * sc);
    }

    // --- NNConv edges: out[dst] += (P_B[src] + sum_k ef[e,k]*P_k[src]) / deg_dst ---
    {
        int sA = pinned_src[e], dA = pinned_dst[e];
        int sB = pf_src[e] + N_NET, dB = pf_dst[e];
        float evA0 = pin_feat[e * 16 + q],  evA1 = pin_feat[e * 16 + 8 + q];
        float evB0 = edge_feat[e * 16 + q], evB1 = edge_feat[e * 16 + 8 + q];

        const __half* PA = g_P + (size_t)sA * 544;
        const __half* PB = g_P + (size_t)sB * 544;

        float4 mA = ldh4(PA + 512 + q * 4);
        float4 mB = ldh4(PB + 512 + q * 4);

#pragma unroll
        for (int k = 0; k < 16; k++) {
            float cA = __shfl_sync(0xffffffffu, (k < 8) ? evA0 : evA1, baseLane + (k & 7));
            float cB = __shfl_sync(0xffffffffu, (k < 8) ? evB0 : evB1, baseLane + (k & 7));
            float4 pA = ldh4(PA + k * 32 + q * 4);
            float4 pB = ldh4(PB + k * 32 + q * 4);
            mA.x = fmaf(cA, pA.x, mA.x); mA.y = fmaf(cA, pA.y, mA.y);
            mA.z = fmaf(cA, pA.z, mA.z); mA.w = fmaf(cA, pA.w, mA.w);
            mB.x = fmaf(cB, pB.x, mB.x); mB.y = fmaf(cB, pB.y, mB.y);
            mB.z = fmaf(cB, pB.z, mB.z); mB.w = fmaf(cB, pB.w, mB.w);
        }

        float invA = 1.0f / (float)max(g_deg[OFF_PINNED_D + dA], 1);
        float invB = 1.0f / (float)max(g_deg[OFF_PF_D + dB], 1);
        red_add_v4(out_cell + dA * 32 + q * 4, mA.x * invA, mA.y * invA, mA.z * invA, mA.w * invA);
        red_add_v4(out_cell + dB * 32 + q * 4, mB.x * invB, mB.y * invB, mB.z * invB, mB.w * invB);
    }
}

// ---------------------------------------------------------------------------
extern "C" void kernel_launch(void* const* d_in, const int* in_sizes, int n_in,
                              void* d_out, int out_size) {
    const float* node_feat   = (const float*)d_in[0];
    const float* net_feat    = (const float*)d_in[1];
    const float* pin_feat    = (const float*)d_in[2];
    const float* hanna_feat  = (const float*)d_in[3];
    const float* edge_feat   = (const float*)d_in[4];
    const int*   pins_src    = (const int*)d_in[5];
    const int*   pins_dst    = (const int*)d_in[6];
    const int*   pinned_src  = (const int*)d_in[7];
    const int*   pinned_dst  = (const int*)d_in[8];
    const int*   connect_src = (const int*)d_in[9];
    const int*   connect_dst = (const int*)d_in[10];
    const int*   pt_src      = (const int*)d_in[11];
    const int*   pt_dst      = (const int*)d_in[12];
    const int*   pf_src      = (const int*)d_in[13];
    const int*   pf_dst      = (const int*)d_in[14];
    const float* W_net       = (const float*)d_in[15];
    const float* b_net       = (const float*)d_in[16];
    const float* W_topo      = (const float*)d_in[17];
    const float* b_topo      = (const float*)d_in[18];
    const float* W_pins      = (const float*)d_in[19];
    const float* b_pins      = (const float*)d_in[20];
    const float* W_connect   = (const float*)d_in[21];
    const float* b_connect   = (const float*)d_in[22];
    const float* W_pt        = (const float*)d_in[23];
    const float* b_pt        = (const float*)d_in[24];
    const float* b_pinned    = (const float*)d_in[25];
    const float* b_pf        = (const float*)d_in[26];

    float* out       = (float*)d_out;
    float* out_net   = out + (size_t)N_CELL * D;
    float* out_gcell = out + (size_t)(N_CELL + N_NET) * D;

    // K1: fused init (zero degrees + bias-sum output init), vectorized
    init_fused_kernel<<<(INIT_V4 + 255) / 256, 256>>>(out, b_pinned, b_pf, b_pins, b_net,
                                                      b_connect, b_pt);

    // K2: degree counting overlapped with P-GEMM (independent work, one launch)
    degree_pgemm_kernel<<<K2_BLOCKS, 256>>>(net_feat, hanna_feat, W_topo,
                                            pins_src, pins_dst, connect_src, connect_dst,
                                            pt_src, pt_dst, pinned_dst, pf_dst);

    // K3: remaining dense jobs (v3 tiles — measured best; fp16 feat outputs)
    dense_rest_kernel<<<NB_REST, 256>>>(node_feat, net_feat, hanna_feat,
                                        b_topo, W_pins, W_pt, W_connect, W_net, out_net);

    // K4: all 5 edge relations (R13 proven kernel + fp16 feat gathers)
    const int EGRID = (E / 4 * 32 + 255) / 256;   // 3125 blocks
    edge_kernel<<<EGRID, 256>>>(pins_src, pins_dst, connect_src, connect_dst,
                                pt_src, pt_dst, pinned_src, pinned_dst, pf_src, pf_dst,
                                pin_feat, edge_feat, out, out_net, out_gcell);
}